// round 2
// baseline (speedup 1.0000x reference)
#include <cuda_runtime.h>

#define T_TOK   8192
#define F_DIM   256
#define NMAX    8192
#define TILES   128
#define TILE_T  (T_TOK / TILES)   // 64 rows per tile

// scratch for two-level scan: per-tile column sums (TILES x F) = 128KB
__device__ float g_tilesum[TILES * F_DIM];

// K0: zero the output (used as the difference array). float4 stores.
__global__ void k_zero(float4* out) {
    int i = blockIdx.x * blockDim.x + threadIdx.x;
    out[i] = make_float4(0.f, 0.f, 0.f, 0.f);
}

// K1: scatter. One block per node, 64 threads, each thread 4 features (float4 load).
// add emb[n] at row start, subtract at row end+1 (if within range).
__global__ void k_scatter(const float4* __restrict__ emb,
                          const int* __restrict__ starts,
                          const int* __restrict__ ends,
                          const int* __restrict__ num_nodes,
                          float* __restrict__ out) {
    int n = blockIdx.x;
    if (n >= *num_nodes) return;
    int s = starts[n];
    int e = ends[n];
    if (s > e) return;                 // empty span contributes nothing
    int f4 = threadIdx.x;              // 0..63
    float4 v = emb[n * (F_DIM / 4) + f4];

    float* row = out + (size_t)s * F_DIM + f4 * 4;
    atomicAdd(row + 0, v.x);
    atomicAdd(row + 1, v.y);
    atomicAdd(row + 2, v.z);
    atomicAdd(row + 3, v.w);

    if (e + 1 < T_TOK) {
        float* row2 = out + (size_t)(e + 1) * F_DIM + f4 * 4;
        atomicAdd(row2 + 0, -v.x);
        atomicAdd(row2 + 1, -v.y);
        atomicAdd(row2 + 2, -v.z);
        atomicAdd(row2 + 3, -v.w);
    }
}

// K2: per-tile column sums. blockIdx = tile, threadIdx = feature.
// Row-major layout -> fully coalesced (block reads one 1KB row at a time).
__global__ void k_tilesum(const float* __restrict__ data) {
    int tile = blockIdx.x;
    int f = threadIdx.x;
    const float* p = data + (size_t)tile * TILE_T * F_DIM + f;
    float s = 0.f;
#pragma unroll
    for (int t = 0; t < TILE_T; t++)
        s += p[(size_t)t * F_DIM];
    g_tilesum[tile * F_DIM + f] = s;
}

// K3: exclusive scan of tile sums along the tile axis. One block, thread = feature.
__global__ void k_scantiles() {
    int f = threadIdx.x;
    float run = 0.f;
#pragma unroll
    for (int tile = 0; tile < TILES; tile++) {
        float v = g_tilesum[tile * F_DIM + f];
        g_tilesum[tile * F_DIM + f] = run;   // exclusive prefix
        run += v;
    }
}

// K4: in-place cumsum within each tile, seeded by the tile's exclusive offset.
// Each element is read then overwritten by the same thread -> in-place safe.
__global__ void k_cumsum(float* __restrict__ data) {
    int tile = blockIdx.x;
    int f = threadIdx.x;
    float run = g_tilesum[tile * F_DIM + f];
    float* p = data + (size_t)tile * TILE_T * F_DIM + f;
#pragma unroll
    for (int t = 0; t < TILE_T; t++) {
        run += p[(size_t)t * F_DIM];
        p[(size_t)t * F_DIM] = run;
    }
}

extern "C" void kernel_launch(void* const* d_in, const int* in_sizes, int n_in,
                              void* d_out, int out_size) {
    const float4* emb   = (const float4*)d_in[0];   // [8192, 256] f32
    const int*    starts = (const int*)d_in[1];     // [8192] i32
    const int*    ends   = (const int*)d_in[2];     // [8192] i32
    const int*    nn     = (const int*)d_in[3];     // scalar i32 (device)
    float* out = (float*)d_out;                     // [8192, 256] f32

    // zero diff buffer (= output buffer)
    k_zero<<<(T_TOK * F_DIM / 4) / 256, 256>>>((float4*)out);
    // scatter span edges
    k_scatter<<<NMAX, 64>>>(emb, starts, ends, nn, out);
    // two-level prefix scan along token axis
    k_tilesum<<<TILES, F_DIM>>>(out);
    k_scantiles<<<1, F_DIM>>>();
    k_cumsum<<<TILES, F_DIM>>>(out);
}

// round 7
// speedup vs baseline: 1.1758x; 1.1758x over previous
#include <cuda_runtime.h>

#define T_TOK   8192
#define F_DIM   256
#define NMAX    8192
#define TILES   128
#define TILE_T  (T_TOK / TILES)   // 64 rows per tile

// scratch: per-tile column sums (TILES x F) = 128KB, L2-resident
__device__ float g_tilesum[TILES * F_DIM];

// K0: zero the output (used as the difference array). float4 stores.
__global__ void k_zero(float4* out) {
    int i = blockIdx.x * blockDim.x + threadIdx.x;
    out[i] = make_float4(0.f, 0.f, 0.f, 0.f);
}

// K1: scatter. One block per node, 64 threads, each thread 4 features (float4 load).
// add emb[n] at row start, subtract at row end+1 (if within range).
__global__ void k_scatter(const float4* __restrict__ emb,
                          const int* __restrict__ starts,
                          const int* __restrict__ ends,
                          const int* __restrict__ num_nodes,
                          float* __restrict__ out) {
    int n = blockIdx.x;
    if (n >= *num_nodes) return;
    int s = starts[n];
    int e = ends[n];
    if (s > e) return;                 // empty span contributes nothing
    int f4 = threadIdx.x;              // 0..63
    float4 v = emb[n * (F_DIM / 4) + f4];

    float* row = out + (size_t)s * F_DIM + f4 * 4;
    atomicAdd(row + 0, v.x);
    atomicAdd(row + 1, v.y);
    atomicAdd(row + 2, v.z);
    atomicAdd(row + 3, v.w);

    if (e + 1 < T_TOK) {
        float* row2 = out + (size_t)(e + 1) * F_DIM + f4 * 4;
        atomicAdd(row2 + 0, -v.x);
        atomicAdd(row2 + 1, -v.y);
        atomicAdd(row2 + 2, -v.z);
        atomicAdd(row2 + 3, -v.w);
    }
}

// K2: per-tile column sums. blockIdx = tile, threadIdx = feature.
// Row-major layout -> fully coalesced (block reads one 1KB row at a time).
__global__ void k_tilesum(const float* __restrict__ data) {
    int tile = blockIdx.x;
    int f = threadIdx.x;
    const float* p = data + (size_t)tile * TILE_T * F_DIM + f;
    float s = 0.f;
#pragma unroll
    for (int t = 0; t < TILE_T; t++)
        s += p[(size_t)t * F_DIM];
    g_tilesum[tile * F_DIM + f] = s;
}

// K3 (fused): each block computes its own exclusive tile-offset by summing
// all preceding tile sums (L2-resident, independent loads -> pipelined),
// then does the in-place cumsum within its tile. Replaces the serial
// single-block scan kernel entirely.
__global__ void k_cumsum(float* __restrict__ data) {
    int tile = blockIdx.x;
    int f = threadIdx.x;

    // exclusive prefix over tiles 0..tile-1 (fixed ascending order -> deterministic)
    float run = 0.f;
    const float* ts = g_tilesum + f;
    for (int p = 0; p < tile; p++)
        run += ts[p * F_DIM];

    float* p = data + (size_t)tile * TILE_T * F_DIM + f;
#pragma unroll
    for (int t = 0; t < TILE_T; t++) {
        run += p[(size_t)t * F_DIM];
        p[(size_t)t * F_DIM] = run;
    }
}

extern "C" void kernel_launch(void* const* d_in, const int* in_sizes, int n_in,
                              void* d_out, int out_size) {
    const float4* emb    = (const float4*)d_in[0];  // [8192, 256] f32
    const int*    starts = (const int*)d_in[1];     // [8192] i32
    const int*    ends   = (const int*)d_in[2];     // [8192] i32
    const int*    nn     = (const int*)d_in[3];     // scalar i32 (device)
    float* out = (float*)d_out;                     // [8192, 256] f32

    // zero diff buffer (= output buffer)
    k_zero<<<(T_TOK * F_DIM / 4) / 256, 256>>>((float4*)out);
    // scatter span edges
    k_scatter<<<NMAX, 64>>>(emb, starts, ends, nn, out);
    // tile sums, then fused offset+cumsum
    k_tilesum<<<TILES, F_DIM>>>(out);
    k_cumsum<<<TILES, F_DIM>>>(out);
}